// round 1
// baseline (speedup 1.0000x reference)
#include <cuda_runtime.h>
#include <cuda_bf16.h>

// Problem constants: B=4, N=256, D=128, M=128, C=128
#define BB 4
#define NN 256
#define DD 128
#define MM 128
#define CC 128

// Scratch (device globals — no allocation allowed)
__device__ float g_pi[BB * NN * MM];    // h @ W1a
__device__ float g_pjb[BB * NN * MM];   // h @ W1b + b1

__device__ __forceinline__ float siluf(float x) {
    // x * sigmoid(x) = x / (1 + exp(-x)); fast path: MUFU EX2 + MUFU RCP
    return __fdividef(x, 1.0f + __expf(-x));
}

// ---------------------------------------------------------------------------
// Kernel 1: projection. 128 blocks x 128 threads, 8 rows per block.
// pi[row, m] = sum_d h[row, d] * W1a[d, m]
// pjb[row, m] = sum_d h[row, d] * W1b[d, m] + b1[m]
// ---------------------------------------------------------------------------
__global__ void __launch_bounds__(128) proj_kernel(
    const float* __restrict__ h,
    const float* __restrict__ W1a,
    const float* __restrict__ W1b,
    const float* __restrict__ b1)
{
    const int row0 = blockIdx.x * 8;
    const int t = threadIdx.x;

    __shared__ float hsh[8][DD];
    #pragma unroll
    for (int r = 0; r < 8; r++)
        hsh[r][t] = h[(size_t)(row0 + r) * DD + t];
    __syncthreads();

    float pi[8], pj[8];
    #pragma unroll
    for (int r = 0; r < 8; r++) { pi[r] = 0.f; pj[r] = 0.f; }

    #pragma unroll 4
    for (int d = 0; d < DD; d++) {
        const float wa = W1a[d * MM + t];
        const float wb = W1b[d * MM + t];
        #pragma unroll
        for (int r = 0; r < 8; r++) {
            pi[r] = fmaf(hsh[r][d], wa, pi[r]);
            pj[r] = fmaf(hsh[r][d], wb, pj[r]);
        }
    }

    const float bb = b1[t];
    #pragma unroll
    for (int r = 0; r < 8; r++) {
        g_pi[(size_t)(row0 + r) * MM + t]  = pi[r];
        g_pjb[(size_t)(row0 + r) * MM + t] = pj[r] + bb;
    }
}

// ---------------------------------------------------------------------------
// Kernel 2: main. One block per (b, i). 256 threads = 8 j-lanes x 32 m-lanes.
// acc[m] = sum_{j != i} adj[b,i,j] * silu(pi[b,i,m] + pjb[b,j,m])
// m_agg[k] = (acc @ W2 [k] + b2[k]*S) / denom
// out = silu(m_agg @ Wc1 + bc1) @ Wc2 + bc2
// ---------------------------------------------------------------------------
__global__ void __launch_bounds__(256) main_kernel(
    const float* __restrict__ adj,
    const float* __restrict__ W2,
    const float* __restrict__ b2,
    const float* __restrict__ Wc1,
    const float* __restrict__ bc1,
    const float* __restrict__ Wc2,
    const float* __restrict__ bc2,
    float* __restrict__ out)
{
    const int bi = blockIdx.x;          // 0..1023
    const int b  = bi >> 8;
    const int i  = bi & (NN - 1);
    const int t  = threadIdx.x;

    __shared__ float adj_sh[NN];
    __shared__ float accsh[8][MM];
    __shared__ float wsum[8];
    __shared__ float sacc[MM];
    __shared__ float smagg[MM];
    __shared__ float shid[MM];

    // Load adj row, block-reduce its sum
    const float* adjrow = adj + (size_t)bi * NN;
    float av = adjrow[t];
    adj_sh[t] = av;
    #pragma unroll
    for (int o = 16; o; o >>= 1) av += __shfl_xor_sync(0xFFFFFFFFu, av, o);
    if ((t & 31) == 0) wsum[t >> 5] = av;
    __syncthreads();

    float sum_all = 0.f;
    #pragma unroll
    for (int g = 0; g < 8; g++) sum_all += wsum[g];
    const float adj_ii = adj_sh[i];
    const float S      = sum_all - adj_ii;
    const float denom  = fmaxf(sum_all, 1.0f);
    const float inv_d  = __fdividef(1.0f, denom);

    const int tm = t & 31;   // m-group: covers m = 4*tm .. 4*tm+3
    const int jj = t >> 5;   // j-lane 0..7

    const float4 pi4 = *reinterpret_cast<const float4*>(g_pi + (size_t)bi * MM + tm * 4);
    const float* pjb_b = g_pjb + (size_t)b * NN * MM;

    float4 acc = make_float4(0.f, 0.f, 0.f, 0.f);

    #pragma unroll 4
    for (int j = jj; j < NN; j += 8) {
        const float w = (j == i) ? 0.f : adj_sh[j];
        const float4 p = *reinterpret_cast<const float4*>(pjb_b + (size_t)j * MM + tm * 4);
        acc.x = fmaf(w, siluf(pi4.x + p.x), acc.x);
        acc.y = fmaf(w, siluf(pi4.y + p.y), acc.y);
        acc.z = fmaf(w, siluf(pi4.z + p.z), acc.z);
        acc.w = fmaf(w, siluf(pi4.w + p.w), acc.w);
    }

    *reinterpret_cast<float4*>(&accsh[jj][tm * 4]) = acc;
    __syncthreads();

    // Reduce across the 8 j-lanes
    if (t < MM) {
        float v = 0.f;
        #pragma unroll
        for (int g = 0; g < 8; g++) v += accsh[g][t];
        sacc[t] = v;
    }
    __syncthreads();

    // m_agg = (sacc @ W2 + b2*S) / denom
    if (t < MM) {
        float v = b2[t] * S;
        #pragma unroll 8
        for (int m2 = 0; m2 < MM; m2++)
            v = fmaf(sacc[m2], W2[m2 * MM + t], v);
        smagg[t] = v * inv_d;
    }
    __syncthreads();

    // hidden = silu(m_agg @ Wc1 + bc1)
    if (t < MM) {
        float u = bc1[t];
        #pragma unroll 8
        for (int m2 = 0; m2 < MM; m2++)
            u = fmaf(smagg[m2], Wc1[m2 * MM + t], u);
        shid[t] = siluf(u);
    }
    __syncthreads();

    // out = hidden @ Wc2 + bc2
    if (t < CC) {
        float o = bc2[t];
        #pragma unroll 8
        for (int m2 = 0; m2 < MM; m2++)
            o = fmaf(shid[m2], Wc2[m2 * CC + t], o);
        out[(size_t)bi * CC + t] = o;
    }
}

// ---------------------------------------------------------------------------
// Launch
// ---------------------------------------------------------------------------
extern "C" void kernel_launch(void* const* d_in, const int* in_sizes, int n_in,
                              void* d_out, int out_size)
{
    const float* h   = (const float*)d_in[0];
    const float* adj = (const float*)d_in[1];
    const float* W1a = (const float*)d_in[2];
    const float* W1b = (const float*)d_in[3];
    const float* b1  = (const float*)d_in[4];
    const float* W2  = (const float*)d_in[5];
    const float* b2  = (const float*)d_in[6];
    const float* Wc1 = (const float*)d_in[7];
    const float* bc1 = (const float*)d_in[8];
    const float* Wc2 = (const float*)d_in[9];
    const float* bc2 = (const float*)d_in[10];
    float* out = (float*)d_out;

    proj_kernel<<<(BB * NN) / 8, 128>>>(h, W1a, W1b, b1);
    main_kernel<<<BB * NN, 256>>>(adj, W2, b2, Wc1, bc1, Wc2, bc2, out);
}

// round 2
// speedup vs baseline: 1.1625x; 1.1625x over previous
#include <cuda_runtime.h>
#include <cuda_bf16.h>

// Problem constants: B=4, N=256, D=128, M=128, C=128
#define BB 4
#define NN 256
#define DD 128
#define MM 128
#define CC 128

// Scratch (device globals — no allocation allowed)
// NOTE: both are PRE-SCALED by 0.5 so that hx = g_pi + g_pjb = pre/2,
// and silu(pre) = hx + hx*tanh(hx).
__device__ float g_pi[BB * NN * MM];    // 0.5 * (h @ W1a)
__device__ float g_pjb[BB * NN * MM];   // 0.5 * (h @ W1b + b1)

__device__ __forceinline__ float tanh_approx(float x) {
    float y;
    asm("tanh.approx.f32 %0, %1;" : "=f"(y) : "f"(x));
    return y;
}

__device__ __forceinline__ float siluf(float x) {
    // exact-ish silu for the (tiny) epilogue — keep accuracy there
    return __fdividef(x, 1.0f + __expf(-x));
}

// ---------------------------------------------------------------------------
// Kernel 1: projection. 128 blocks x 128 threads, 8 rows per block.
// ---------------------------------------------------------------------------
__global__ void __launch_bounds__(128) proj_kernel(
    const float* __restrict__ h,
    const float* __restrict__ W1a,
    const float* __restrict__ W1b,
    const float* __restrict__ b1)
{
    const int row0 = blockIdx.x * 8;
    const int t = threadIdx.x;

    __shared__ float hsh[8][DD];
    #pragma unroll
    for (int r = 0; r < 8; r++)
        hsh[r][t] = h[(size_t)(row0 + r) * DD + t];
    __syncthreads();

    float pi[8], pj[8];
    #pragma unroll
    for (int r = 0; r < 8; r++) { pi[r] = 0.f; pj[r] = 0.f; }

    #pragma unroll 4
    for (int d = 0; d < DD; d++) {
        const float wa = W1a[d * MM + t];
        const float wb = W1b[d * MM + t];
        #pragma unroll
        for (int r = 0; r < 8; r++) {
            pi[r] = fmaf(hsh[r][d], wa, pi[r]);
            pj[r] = fmaf(hsh[r][d], wb, pj[r]);
        }
    }

    const float bb = b1[t];
    #pragma unroll
    for (int r = 0; r < 8; r++) {
        g_pi[(size_t)(row0 + r) * MM + t]  = 0.5f * pi[r];
        g_pjb[(size_t)(row0 + r) * MM + t] = 0.5f * (pj[r] + bb);
    }
}

// ---------------------------------------------------------------------------
// Kernel 2: main. One block per (b, i). 256 threads = 8 j-lanes x 32 m-lanes.
// acc[m] = sum_{j != i} adj[b,i,j] * silu(pre[i,j,m])   via tanh.approx
// then 3 fused matvecs (each output computed as 2 half-dots over 256 threads)
// ---------------------------------------------------------------------------
__global__ void __launch_bounds__(256) main_kernel(
    const float* __restrict__ adj,
    const float* __restrict__ W2,
    const float* __restrict__ b2,
    const float* __restrict__ Wc1,
    const float* __restrict__ bc1,
    const float* __restrict__ Wc2,
    const float* __restrict__ bc2,
    float* __restrict__ out)
{
    const int bi = blockIdx.x;          // 0..1023
    const int b  = bi >> 8;
    const int i  = bi & (NN - 1);
    const int t  = threadIdx.x;

    __shared__ float adj_sh[NN];
    __shared__ float accsh[8][MM];
    __shared__ float wsum[8];
    __shared__ float sacc[MM];
    __shared__ float parts[2][MM];
    __shared__ float smagg[MM];
    __shared__ float shid[MM];

    // Load adj row, block-reduce its sum
    const float* adjrow = adj + (size_t)bi * NN;
    float av = adjrow[t];
    adj_sh[t] = av;
    #pragma unroll
    for (int o = 16; o; o >>= 1) av += __shfl_xor_sync(0xFFFFFFFFu, av, o);
    if ((t & 31) == 0) wsum[t >> 5] = av;
    __syncthreads();

    float sum_all = 0.f;
    #pragma unroll
    for (int g = 0; g < 8; g++) sum_all += wsum[g];
    const float adj_ii = adj_sh[i];
    const float S      = sum_all - adj_ii;
    const float denom  = fmaxf(sum_all, 1.0f);
    const float inv_d  = __fdividef(1.0f, denom);
    __syncthreads();
    if (t == 0) adj_sh[i] = 0.0f;   // fold the j==i mask into the weights
    __syncthreads();

    const int tm = t & 31;   // m-group: covers m = 4*tm .. 4*tm+3
    const int jj = t >> 5;   // j-lane 0..7

    const float4 pi4 = *reinterpret_cast<const float4*>(g_pi + (size_t)bi * MM + tm * 4);
    const float* pjb_b = g_pjb + (size_t)b * NN * MM;

    float4 acc = make_float4(0.f, 0.f, 0.f, 0.f);

    #pragma unroll 4
    for (int j = jj; j < NN; j += 8) {
        const float w = adj_sh[j];
        const float4 p = *reinterpret_cast<const float4*>(pjb_b + (size_t)j * MM + tm * 4);
        // hx = pre/2 ; silu(pre) = hx + hx*tanh(hx)
        float hx0 = pi4.x + p.x;
        float hx1 = pi4.y + p.y;
        float hx2 = pi4.z + p.z;
        float hx3 = pi4.w + p.w;
        float t0 = tanh_approx(hx0);
        float t1 = tanh_approx(hx1);
        float t2 = tanh_approx(hx2);
        float t3 = tanh_approx(hx3);
        float s0 = fmaf(hx0, t0, hx0);
        float s1 = fmaf(hx1, t1, hx1);
        float s2 = fmaf(hx2, t2, hx2);
        float s3 = fmaf(hx3, t3, hx3);
        acc.x = fmaf(w, s0, acc.x);
        acc.y = fmaf(w, s1, acc.y);
        acc.z = fmaf(w, s2, acc.z);
        acc.w = fmaf(w, s3, acc.w);
    }

    *reinterpret_cast<float4*>(&accsh[jj][tm * 4]) = acc;
    __syncthreads();

    // Reduce across the 8 j-lanes
    if (t < MM) {
        float v = 0.f;
        #pragma unroll
        for (int g = 0; g < 8; g++) v += accsh[g][t];
        sacc[t] = v;
    }
    __syncthreads();

    // ---- epilogue: 3 matvecs, each output split as 2 half-dots over 256 thr
    const int col  = t & (MM - 1);
    const int half = t >> 7;           // 0 or 1
    const int m0   = half * (MM / 2);  // 0 or 64

    // m_agg = (sacc @ W2 + b2*S) / denom
    {
        float v = (half == 0) ? b2[col] * S : 0.0f;
        #pragma unroll 8
        for (int m2 = m0; m2 < m0 + MM / 2; m2++)
            v = fmaf(sacc[m2], W2[m2 * MM + col], v);
        parts[half][col] = v;
    }
    __syncthreads();
    if (t < MM) smagg[t] = (parts[0][t] + parts[1][t]) * inv_d;
    __syncthreads();

    // hidden = silu(m_agg @ Wc1 + bc1)
    {
        float v = (half == 0) ? bc1[col] : 0.0f;
        #pragma unroll 8
        for (int m2 = m0; m2 < m0 + MM / 2; m2++)
            v = fmaf(smagg[m2], Wc1[m2 * MM + col], v);
        parts[half][col] = v;
    }
    __syncthreads();
    if (t < MM) shid[t] = siluf(parts[0][t] + parts[1][t]);
    __syncthreads();

    // out = hidden @ Wc2 + bc2
    {
        float v = (half == 0) ? bc2[col] : 0.0f;
        #pragma unroll 8
        for (int m2 = m0; m2 < m0 + MM / 2; m2++)
            v = fmaf(shid[m2], Wc2[m2 * CC + col], v);
        parts[half][col] = v;
    }
    __syncthreads();
    if (t < CC) out[(size_t)bi * CC + t] = parts[0][t] + parts[1][t];
}

// ---------------------------------------------------------------------------
// Launch
// ---------------------------------------------------------------------------
extern "C" void kernel_launch(void* const* d_in, const int* in_sizes, int n_in,
                              void* d_out, int out_size)
{
    const float* h   = (const float*)d_in[0];
    const float* adj = (const float*)d_in[1];
    const float* W1a = (const float*)d_in[2];
    const float* W1b = (const float*)d_in[3];
    const float* b1  = (const float*)d_in[4];
    const float* W2  = (const float*)d_in[5];
    const float* b2  = (const float*)d_in[6];
    const float* Wc1 = (const float*)d_in[7];
    const float* bc1 = (const float*)d_in[8];
    const float* Wc2 = (const float*)d_in[9];
    const float* bc2 = (const float*)d_in[10];
    float* out = (float*)d_out;

    proj_kernel<<<(BB * NN) / 8, 128>>>(h, W1a, W1b, b1);
    main_kernel<<<BB * NN, 256>>>(adj, W2, b2, Wc1, bc1, Wc2, bc2, out);
}

// round 4
// speedup vs baseline: 1.2880x; 1.1080x over previous
#include <cuda_runtime.h>
#include <cuda_bf16.h>

// Problem constants: B=4, N=256, D=128, M=128, C=128
#define BB 4
#define NN 256
#define DD 128
#define MM 128
#define CC 128

// Scratch (device globals — no allocation allowed)
// Both PRE-SCALED by 0.5 so hx = g_pi + g_pjb = pre/2, silu(pre)=hx+hx*tanh(hx)
__device__ float g_pi[BB * NN * MM];
__device__ float g_pjb[BB * NN * MM];
__device__ float g_W2c[MM * MM];   // W2 @ Wc1
__device__ float g_b2c[MM];        // b2 @ Wc1

__device__ __forceinline__ float tanh_approx(float x) {
    float y;
    asm("tanh.approx.f32 %0, %1;" : "=f"(y) : "f"(x));
    return y;
}
__device__ __forceinline__ float siluf(float x) {
    return __fdividef(x, 1.0f + __expf(-x));
}

// ---------------------------------------------------------------------------
// Prep kernel: 321 blocks x 256 threads.
//  blocks [0,256):  projection, 4 rows per block
//  blocks [256,320): W2c = W2 @ Wc1, 2 m-rows per block
//  block 320:       b2c = b2 @ Wc1
// ---------------------------------------------------------------------------
__global__ void __launch_bounds__(256) prep_kernel(
    const float* __restrict__ h,
    const float* __restrict__ W1a,
    const float* __restrict__ W1b,
    const float* __restrict__ b1,
    const float* __restrict__ W2,
    const float* __restrict__ b2,
    const float* __restrict__ Wc1)
{
    const int t = threadIdx.x;

    if (blockIdx.x < 256) {
        // ---- projection: 4 rows per block (4*128 = 512 floats) ----
        const int row0 = blockIdx.x * 4;
        const int col  = t & 127;
        const int rh   = (t >> 7) * 2;         // 0 or 2: this thread's row pair

        __shared__ float hsh[4][DD];
        // load 512 floats with 256 threads: 2 iterations
        #pragma unroll
        for (int k = 0; k < 2; k++) {
            int idx = k * 256 + t;             // 0..511
            hsh[idx >> 7][idx & 127] = h[(size_t)row0 * DD + idx];
        }
        __syncthreads();

        float a0 = 0.f, a1 = 0.f, p0 = 0.f, p1 = 0.f;
        #pragma unroll 8
        for (int d = 0; d < DD; d++) {
            const float wa = W1a[d * MM + col];
            const float wb = W1b[d * MM + col];
            const float h0 = hsh[rh][d];
            const float h1 = hsh[rh + 1][d];
            a0 = fmaf(h0, wa, a0);
            a1 = fmaf(h1, wa, a1);
            p0 = fmaf(h0, wb, p0);
            p1 = fmaf(h1, wb, p1);
        }
        const float bb = b1[col];
        const int r0 = row0 + rh;
        g_pi[(size_t)r0 * MM + col]        = 0.5f * a0;
        g_pi[(size_t)(r0 + 1) * MM + col]  = 0.5f * a1;
        g_pjb[(size_t)r0 * MM + col]       = 0.5f * (p0 + bb);
        g_pjb[(size_t)(r0 + 1) * MM + col] = 0.5f * (p1 + bb);
    } else if (blockIdx.x < 320) {
        // ---- W2c: 2 m-rows per block ----
        const int m  = (blockIdx.x - 256) * 2 + (t >> 7);
        const int k  = t & 127;

        __shared__ float w2row[2][MM];
        w2row[t >> 7][k] = W2[m * MM + k];
        __syncthreads();

        float v0 = 0.f, v1 = 0.f;
        #pragma unroll 8
        for (int l = 0; l < MM; l += 2) {
            v0 = fmaf(w2row[t >> 7][l],     Wc1[l * MM + k],       v0);
            v1 = fmaf(w2row[t >> 7][l + 1], Wc1[(l + 1) * MM + k], v1);
        }
        g_W2c[m * MM + k] = v0 + v1;
    } else {
        // ---- b2c ----
        if (t < MM) {
            float v = 0.f;
            #pragma unroll 8
            for (int l = 0; l < MM; l++)
                v = fmaf(b2[l], Wc1[l * MM + t], v);
            g_b2c[t] = v;
        }
    }
}

// ---------------------------------------------------------------------------
// Main kernel: one block per (b,i). 256 threads = 8 j-lanes x 32 m-lanes.
// ---------------------------------------------------------------------------
__global__ void __launch_bounds__(256) main_kernel(
    const float* __restrict__ adj,
    const float* __restrict__ bc1,
    const float* __restrict__ Wc2,
    const float* __restrict__ bc2,
    float* __restrict__ out)
{
    const int bi = blockIdx.x;          // 0..1023
    const int b  = bi >> 8;
    const int i  = bi & (NN - 1);
    const int t  = threadIdx.x;

    __shared__ float adj_sh[NN];
    __shared__ float accsh[8][MM];
    __shared__ float wsum[8];
    __shared__ float sacc[MM];
    __shared__ float parts[2][MM];
    __shared__ float shid[MM];

    // Load adj row; store diagonal-masked copy; reduce full sum
    const float* adjrow = adj + (size_t)bi * NN;
    float av = adjrow[t];
    adj_sh[t] = (t == i) ? 0.0f : av;       // fold the j==i mask in
    const float adj_ii = adjrow[i];         // broadcast load
    #pragma unroll
    for (int o = 16; o; o >>= 1) av += __shfl_xor_sync(0xFFFFFFFFu, av, o);
    if ((t & 31) == 0) wsum[t >> 5] = av;
    __syncthreads();

    float sum_all = 0.f;
    #pragma unroll
    for (int g = 0; g < 8; g++) sum_all += wsum[g];
    const float S     = sum_all - adj_ii;
    const float inv_d = __fdividef(1.0f, fmaxf(sum_all, 1.0f));

    const int tm = t & 31;   // m-group: m = 4*tm .. 4*tm+3
    const int jj = t >> 5;   // j-lane 0..7 (uniform within a warp)

    const float4 pi4 = *reinterpret_cast<const float4*>(g_pi + (size_t)bi * MM + tm * 4);
    const float* base = g_pjb + (size_t)b * NN * MM + tm * 4;

    float4 acc = make_float4(0.f, 0.f, 0.f, 0.f);

    // Software-pipelined: 4 float4 loads in flight, use deferred one iteration
    float4 p[4];
    #pragma unroll
    for (int u = 0; u < 4; u++)
        p[u] = *reinterpret_cast<const float4*>(base + (size_t)(jj + u * 8) * MM);

    #pragma unroll
    for (int jo = 0; jo < NN; jo += 32) {
        const int j = jo + jj;
        float4 q[4];
        {
            // clamp prefetch index on the last iteration (loads valid memory,
            // values never consumed)
            const int jn = (jo + 32 < NN) ? (j + 32) : j;
            #pragma unroll
            for (int u = 0; u < 4; u++)
                q[u] = *reinterpret_cast<const float4*>(base + (size_t)(jn + u * 8) * MM);
        }
        #pragma unroll
        for (int u = 0; u < 4; u++) {
            const float w = adj_sh[j + u * 8];
            float hx0 = pi4.x + p[u].x;
            float hx1 = pi4.y + p[u].y;
            float hx2 = pi4.z + p[u].z;
            float hx3 = pi4.w + p[u].w;
            float s0 = fmaf(hx0, tanh_approx(hx0), hx0);
            float s1 = fmaf(hx1, tanh_approx(hx1), hx1);
            float s2 = fmaf(hx2, tanh_approx(hx2), hx2);
            float s3 = fmaf(hx3, tanh_approx(hx3), hx3);
            acc.x = fmaf(w, s0, acc.x);
            acc.y = fmaf(w, s1, acc.y);
            acc.z = fmaf(w, s2, acc.z);
            acc.w = fmaf(w, s3, acc.w);
        }
        #pragma unroll
        for (int u = 0; u < 4; u++) p[u] = q[u];
    }

    *reinterpret_cast<float4*>(&accsh[jj][tm * 4]) = acc;
    __syncthreads();

    if (t < MM) {
        float v = 0.f;
        #pragma unroll
        for (int g = 0; g < 8; g++) v += accsh[g][t];
        sacc[t] = v;
    }
    __syncthreads();

    // ---- epilogue: 2 matvecs (W2@Wc1 pre-folded) ----
    const int col  = t & (MM - 1);
    const int half = t >> 7;
    const int m0   = half * (MM / 2);

    // pre_c1 = (sacc @ W2c + S*b2c) * inv_d + bc1 ; hid = silu(pre_c1)
    {
        float v0 = 0.f, v1 = 0.f;
        #pragma unroll 8
        for (int m2 = m0; m2 < m0 + MM / 2; m2 += 2) {
            v0 = fmaf(sacc[m2],     g_W2c[m2 * MM + col],       v0);
            v1 = fmaf(sacc[m2 + 1], g_W2c[(m2 + 1) * MM + col], v1);
        }
        parts[half][col] = v0 + v1;
    }
    __syncthreads();
    if (t < MM) {
        float u = fmaf(parts[0][t] + parts[1][t] + S * g_b2c[t], inv_d, bc1[t]);
        shid[t] = siluf(u);
    }
    __syncthreads();

    // out = hid @ Wc2 + bc2
    {
        float v0 = (half == 0) ? bc2[col] : 0.0f, v1 = 0.f;
        #pragma unroll 8
        for (int m2 = m0; m2 < m0 + MM / 2; m2 += 2) {
            v0 = fmaf(shid[m2],     Wc2[m2 * CC + col],       v0);
            v1 = fmaf(shid[m2 + 1], Wc2[(m2 + 1) * CC + col], v1);
        }
        parts[half][col] = v0 + v1;
    }
    __syncthreads();
    if (t < CC) out[(size_t)bi * CC + t] = parts[0][t] + parts[1][t];
}

// ---------------------------------------------------------------------------
// Launch
// ---------------------------------------------------------------------------
extern "C" void kernel_launch(void* const* d_in, const int* in_sizes, int n_in,
                              void* d_out, int out_size)
{
    const float* h   = (const float*)d_in[0];
    const float* adj = (const float*)d_in[1];
    const float* W1a = (const float*)d_in[2];
    const float* W1b = (const float*)d_in[3];
    const float* b1  = (const float*)d_in[4];
    const float* W2  = (const float*)d_in[5];
    const float* b2  = (const float*)d_in[6];
    const float* Wc1 = (const float*)d_in[7];
    const float* bc1 = (const float*)d_in[8];
    const float* Wc2 = (const float*)d_in[9];
    const float* bc2 = (const float*)d_in[10];
    float* out = (float*)d_out;

    prep_kernel<<<321, 256>>>(h, W1a, W1b, b1, W2, b2, Wc1);
    main_kernel<<<BB * NN, 256>>>(adj, bc1, Wc2, bc2, out);
}

// round 5
// speedup vs baseline: 1.3773x; 1.0693x over previous
#include <cuda_runtime.h>
#include <cuda_bf16.h>

// Problem constants: B=4, N=256, D=128, M=128, C=128
#define BB 4
#define NN 256
#define DD 128
#define MM 128
#define CC 128

// Scratch (device globals — no allocation allowed)
// Both PRE-SCALED by 0.5 so hx = g_pi + g_pjb = pre/2, silu(pre)=hx+hx*tanh(hx)
__device__ float g_pi[BB * NN * MM];
__device__ float g_pjb[BB * NN * MM];
__device__ float g_W2c[MM * MM];   // W2 @ Wc1
__device__ float g_b2c[MM];        // b2 @ Wc1

__device__ __forceinline__ float tanh_approx(float x) {
    float y;
    asm("tanh.approx.f32 %0, %1;" : "=f"(y) : "f"(x));
    return y;
}
__device__ __forceinline__ float siluf(float x) {
    return __fdividef(x, 1.0f + __expf(-x));
}

// ---------------------------------------------------------------------------
// Prep kernel: 321 blocks x 256 threads.
// ---------------------------------------------------------------------------
__global__ void __launch_bounds__(256) prep_kernel(
    const float* __restrict__ h,
    const float* __restrict__ W1a,
    const float* __restrict__ W1b,
    const float* __restrict__ b1,
    const float* __restrict__ W2,
    const float* __restrict__ b2,
    const float* __restrict__ Wc1)
{
    const int t = threadIdx.x;

    if (blockIdx.x < 256) {
        // ---- projection: 4 rows per block (512 floats) ----
        const int row0 = blockIdx.x * 4;
        const int col  = t & 127;
        const int rh   = (t >> 7) * 2;

        __shared__ float hsh[4][DD];
        #pragma unroll
        for (int k = 0; k < 2; k++) {
            int idx = k * 256 + t;
            hsh[idx >> 7][idx & 127] = h[(size_t)row0 * DD + idx];
        }
        __syncthreads();

        float a0 = 0.f, a1 = 0.f, p0 = 0.f, p1 = 0.f;
        #pragma unroll 8
        for (int d = 0; d < DD; d++) {
            const float wa = W1a[d * MM + col];
            const float wb = W1b[d * MM + col];
            const float h0 = hsh[rh][d];
            const float h1 = hsh[rh + 1][d];
            a0 = fmaf(h0, wa, a0);
            a1 = fmaf(h1, wa, a1);
            p0 = fmaf(h0, wb, p0);
            p1 = fmaf(h1, wb, p1);
        }
        const float bb = b1[col];
        const int r0 = row0 + rh;
        g_pi[(size_t)r0 * MM + col]        = 0.5f * a0;
        g_pi[(size_t)(r0 + 1) * MM + col]  = 0.5f * a1;
        g_pjb[(size_t)r0 * MM + col]       = 0.5f * (p0 + bb);
        g_pjb[(size_t)(r0 + 1) * MM + col] = 0.5f * (p1 + bb);
    } else if (blockIdx.x < 320) {
        // ---- W2c = W2 @ Wc1: 2 m-rows per block ----
        const int m  = (blockIdx.x - 256) * 2 + (t >> 7);
        const int k  = t & 127;

        __shared__ float w2row[2][MM];
        w2row[t >> 7][k] = W2[m * MM + k];
        __syncthreads();

        float v0 = 0.f, v1 = 0.f;
        #pragma unroll 8
        for (int l = 0; l < MM; l += 2) {
            v0 = fmaf(w2row[t >> 7][l],     Wc1[l * MM + k],       v0);
            v1 = fmaf(w2row[t >> 7][l + 1], Wc1[(l + 1) * MM + k], v1);
        }
        g_W2c[m * MM + k] = v0 + v1;
    } else {
        // ---- b2c = b2 @ Wc1 ----
        if (t < MM) {
            float v = 0.f;
            #pragma unroll 8
            for (int l = 0; l < MM; l++)
                v = fmaf(b2[l], Wc1[l * MM + t], v);
            g_b2c[t] = v;
        }
    }
}

// ---------------------------------------------------------------------------
// Main kernel: one block per (b,i). 256 threads = 8 j-lanes x 32 m-lanes.
// Distance-2 software pipeline: 8 float4 loads in flight.
// ---------------------------------------------------------------------------
__global__ void __launch_bounds__(256) main_kernel(
    const float* __restrict__ adj,
    const float* __restrict__ bc1,
    const float* __restrict__ Wc2,
    const float* __restrict__ bc2,
    float* __restrict__ out)
{
    const int bi = blockIdx.x;          // 0..1023
    const int b  = bi >> 8;
    const int i  = bi & (NN - 1);
    const int t  = threadIdx.x;

    __shared__ float adj_sh[NN];
    __shared__ float accsh[8][MM];
    __shared__ float wsum[8];
    __shared__ float sacc[MM];
    __shared__ float parts[2][MM];
    __shared__ float shid[MM];

    // Load adj row; diagonal-masked copy; full-row sum
    const float* adjrow = adj + (size_t)bi * NN;
    float av = adjrow[t];
    adj_sh[t] = (t == i) ? 0.0f : av;
    const float adj_ii = adjrow[i];
    #pragma unroll
    for (int o = 16; o; o >>= 1) av += __shfl_xor_sync(0xFFFFFFFFu, av, o);
    if ((t & 31) == 0) wsum[t >> 5] = av;
    __syncthreads();

    float sum_all = 0.f;
    #pragma unroll
    for (int g = 0; g < 8; g++) sum_all += wsum[g];
    const float S     = sum_all - adj_ii;
    const float inv_d = __fdividef(1.0f, fmaxf(sum_all, 1.0f));

    const int tm = t & 31;   // m-quad lane
    const int jj = t >> 5;   // j-lane 0..7 (uniform per warp)

    const float4 pi4 = *reinterpret_cast<const float4*>(g_pi + (size_t)bi * MM + tm * 4);
    const float* base = g_pjb + (size_t)b * NN * MM + tm * 4;

    float4 acc = make_float4(0.f, 0.f, 0.f, 0.f);

    // Distance-2 pipeline: two 4-wide buffers
    float4 p[2][4];
    #pragma unroll
    for (int u = 0; u < 4; u++) {
        p[0][u] = *reinterpret_cast<const float4*>(base + (size_t)(jj + u * 8) * MM);
        p[1][u] = *reinterpret_cast<const float4*>(base + (size_t)(jj + 32 + u * 8) * MM);
    }

    #pragma unroll
    for (int jo = 0; jo < 8; jo++) {
        const int j = jo * 32 + jj;
        float4* cur = p[jo & 1];

        float w[4];
        #pragma unroll
        for (int u = 0; u < 4; u++) w[u] = adj_sh[j + u * 8];

        float4 a2 = make_float4(0.f, 0.f, 0.f, 0.f);
        #pragma unroll
        for (int u = 0; u < 4; u++) {
            float hx0 = pi4.x + cur[u].x;
            float hx1 = pi4.y + cur[u].y;
            float hx2 = pi4.z + cur[u].z;
            float hx3 = pi4.w + cur[u].w;
            float s0 = fmaf(hx0, tanh_approx(hx0), hx0);
            float s1 = fmaf(hx1, tanh_approx(hx1), hx1);
            float s2 = fmaf(hx2, tanh_approx(hx2), hx2);
            float s3 = fmaf(hx3, tanh_approx(hx3), hx3);
            a2.x = fmaf(w[u], s0, a2.x);
            a2.y = fmaf(w[u], s1, a2.y);
            a2.z = fmaf(w[u], s2, a2.z);
            a2.w = fmaf(w[u], s3, a2.w);
        }
        acc.x += a2.x; acc.y += a2.y; acc.z += a2.z; acc.w += a2.w;

        // prefetch for iteration jo+2 into the buffer just consumed
        if (jo < 6) {
            #pragma unroll
            for (int u = 0; u < 4; u++)
                cur[u] = *reinterpret_cast<const float4*>(base + (size_t)(j + 64 + u * 8) * MM);
        }
    }

    *reinterpret_cast<float4*>(&accsh[jj][tm * 4]) = acc;
    __syncthreads();

    if (t < MM) {
        float v = 0.f;
        #pragma unroll
        for (int g = 0; g < 8; g++) v += accsh[g][t];
        sacc[t] = v;
    }
    __syncthreads();

    // ---- epilogue: 2 matvecs (W2@Wc1 pre-folded) ----
    const int col  = t & (MM - 1);
    const int half = t >> 7;
    const int m0   = half * (MM / 2);

    {
        float v0 = 0.f, v1 = 0.f, v2 = 0.f, v3 = 0.f;
        #pragma unroll 4
        for (int m2 = m0; m2 < m0 + MM / 2; m2 += 4) {
            v0 = fmaf(sacc[m2],     g_W2c[m2 * MM + col],       v0);
            v1 = fmaf(sacc[m2 + 1], g_W2c[(m2 + 1) * MM + col], v1);
            v2 = fmaf(sacc[m2 + 2], g_W2c[(m2 + 2) * MM + col], v2);
            v3 = fmaf(sacc[m2 + 3], g_W2c[(m2 + 3) * MM + col], v3);
        }
        parts[half][col] = (v0 + v1) + (v2 + v3);
    }
    __syncthreads();
    if (t < MM) {
        float u = fmaf(parts[0][t] + parts[1][t] + S * g_b2c[t], inv_d, bc1[t]);
        shid[t] = siluf(u);
    }
    __syncthreads();

    {
        float v0 = (half == 0) ? bc2[col] : 0.0f, v1 = 0.f, v2 = 0.f, v3 = 0.f;
        #pragma unroll 4
        for (int m2 = m0; m2 < m0 + MM / 2; m2 += 4) {
            v0 = fmaf(shid[m2],     Wc2[m2 * CC + col],       v0);
            v1 = fmaf(shid[m2 + 1], Wc2[(m2 + 1) * CC + col], v1);
            v2 = fmaf(shid[m2 + 2], Wc2[(m2 + 2) * CC + col], v2);
            v3 = fmaf(shid[m2 + 3], Wc2[(m2 + 3) * CC + col], v3);
        }
        parts[half][col] = (v0 + v1) + (v2 + v3);
    }
    __syncthreads();
    if (t < CC) out[(size_t)bi * CC + t] = parts[0][t] + parts[1][t];
}

// ---------------------------------------------------------------------------
// Launch
// ---------------------------------------------------------------------------
extern "C" void kernel_launch(void* const* d_in, const int* in_sizes, int n_in,
                              void* d_out, int out_size)
{
    const float* h   = (const float*)d_in[0];
    const float* adj = (const float*)d_in[1];
    const float* W1a = (const float*)d_in[2];
    const float* W1b = (const float*)d_in[3];
    const float* b1  = (const float*)d_in[4];
    const float* W2  = (const float*)d_in[5];
    const float* b2  = (const float*)d_in[6];
    const float* Wc1 = (const float*)d_in[7];
    const float* bc1 = (const float*)d_in[8];
    const float* Wc2 = (const float*)d_in[9];
    const float* bc2 = (const float*)d_in[10];
    float* out = (float*)d_out;

    prep_kernel<<<321, 256>>>(h, W1a, W1b, b1, W2, b2, Wc1);
    main_kernel<<<BB * NN, 256>>>(adj, bc1, Wc2, bc2, out);
}